// round 15
// baseline (speedup 1.0000x reference)
#include <cuda_runtime.h>
#include <cuda_fp16.h>
#include <cstdint>
#include <math.h>

#define N_TOK 2048
#define C_DIM 768
#define E_NUM 32
#define H_DIM 3072
#define EPG   4                 // experts per ffn2 CTA (gate folded into h)
#define NGRP  (E_NUM / EPG)     // 8

#define BM 128
#define BN 128
#define BK 32
#define ASTRIDE 40     // 80B rows: 16B-aligned; ldmatrix conflict-free
#define BSTRIDE 136    // 272B rows: 16B-aligned; ldmatrix.trans conflict-free

#define A_ELTS (BM * ASTRIDE)              // 5120
#define B_ELTS (BK * BSTRIDE)              // 4352
#define STAGE_ELTS (A_ELTS + B_ELTS)       // 9472 elts (fp16)
#define NSTAGES 5
#define SMEM_BYTES (NSTAGES * STAGE_ELTS * 2)  // 94720 B -> 2 CTAs/SM

// ---------------- scratch (device globals; no allocation allowed) -----------
__device__ float g_gates[N_TOK * E_NUM];
__device__ __half g_x16[N_TOK * C_DIM];
__device__ __half g_w1h[(size_t)E_NUM * C_DIM * H_DIM];
__device__ __half g_w2h[(size_t)E_NUM * H_DIM * C_DIM];
__device__ __half g_h16[(size_t)E_NUM * N_TOK * H_DIM];   // pre-scaled by gate
__device__ float g_part[(size_t)NGRP * N_TOK * C_DIM];    // 50 MB

// ---------------- helpers ---------------------------------------------------
__device__ __forceinline__ uint32_t smem_u32(const void* p) {
    return (uint32_t)__cvta_generic_to_shared(p);
}
__device__ __forceinline__ void cp16(uint32_t s, const void* g) {
    asm volatile("cp.async.cg.shared.global [%0], [%1], 16;" :: "r"(s), "l"(g));
}
#define CP_COMMIT asm volatile("cp.async.commit_group;" ::: "memory")
#define CP_WAIT3  asm volatile("cp.async.wait_group 3;" ::: "memory")

__device__ __forceinline__ void ldm_x4(uint32_t r[4], uint32_t addr) {
    asm volatile("ldmatrix.sync.aligned.m8n8.x4.shared.b16 {%0,%1,%2,%3}, [%4];"
                 : "=r"(r[0]), "=r"(r[1]), "=r"(r[2]), "=r"(r[3]) : "r"(addr));
}
__device__ __forceinline__ void ldm_x4_t(uint32_t r[4], uint32_t addr) {
    asm volatile("ldmatrix.sync.aligned.m8n8.x4.trans.shared.b16 {%0,%1,%2,%3}, [%4];"
                 : "=r"(r[0]), "=r"(r[1]), "=r"(r[2]), "=r"(r[3]) : "r"(addr));
}
__device__ __forceinline__ void mma16816(float d[4], const uint32_t a[4], const uint32_t b[2]) {
    asm volatile("mma.sync.aligned.m16n8k16.row.col.f32.f16.f16.f32 "
                 "{%0,%1,%2,%3},{%4,%5,%6,%7},{%8,%9},{%0,%1,%2,%3};"
                 : "+f"(d[0]), "+f"(d[1]), "+f"(d[2]), "+f"(d[3])
                 : "r"(a[0]), "r"(a[1]), "r"(a[2]), "r"(a[3]), "r"(b[0]), "r"(b[1]));
}
__device__ __forceinline__ uint2 pack_h4(float4 v) {
    __half2 a = __floats2half2_rn(v.x, v.y);
    __half2 b = __floats2half2_rn(v.z, v.w);
    uint2 r;
    r.x = *reinterpret_cast<uint32_t*>(&a);
    r.y = *reinterpret_cast<uint32_t*>(&b);
    return r;
}
__device__ __forceinline__ float gelu_f(float v) {
    return 0.5f * v * (1.0f + erff(v * 0.70710678118654752f));
}

// single-pass fp16 MMA over one BK=32 stage. 8 warps 4(M)x2(N); warp 32x64.
__device__ __forceinline__ void mma_stage(
    const __half* As, const __half* Bs,
    int lane, int wm, int wn, float acc[2][8][4])
{
#pragma unroll
    for (int kk = 0; kk < 2; kk++) {
        uint32_t a[2][4];
#pragma unroll
        for (int mi = 0; mi < 2; mi++) {
            int off = (wm * 32 + mi * 16 + (lane & 15)) * ASTRIDE + kk * 16 + ((lane >> 4) << 3);
            ldm_x4(a[mi], smem_u32(As + off));
        }
        uint32_t b[4][4];
#pragma unroll
        for (int nj = 0; nj < 4; nj++) {
            int off = (kk * 16 + (lane & 15)) * BSTRIDE + wn * 64 + nj * 16 + ((lane >> 4) << 3);
            ldm_x4_t(b[nj], smem_u32(Bs + off));
        }
#pragma unroll
        for (int mi = 0; mi < 2; mi++) {
#pragma unroll
            for (int n8 = 0; n8 < 8; n8++) {
                mma16816(acc[mi][n8], a[mi], &b[n8 >> 1][(n8 & 1) * 2]);
            }
        }
    }
}

// ---------------- converters -------------------------------------------------
__global__ void convert2_kernel(const float4* __restrict__ s0, uint2* __restrict__ d0,
                                const float4* __restrict__ s1, uint2* __restrict__ d1,
                                int n4)
{
    int i = blockIdx.x * blockDim.x + threadIdx.x;
    if (i < n4) d0[i] = pack_h4(s0[i]);
    else if (i < 2 * n4) d1[i - n4] = pack_h4(s1[i - n4]);
}
__global__ void convert_kernel(const float4* __restrict__ src,
                               uint2* __restrict__ dst, int n4)
{
    int i = blockIdx.x * blockDim.x + threadIdx.x;
    if (i >= n4) return;
    dst[i] = pack_h4(src[i]);
}

// ---------------- gating softmax ---------------------------------------------
__global__ void gate_kernel(const float* __restrict__ x,
                            const float* __restrict__ gw,
                            const float* __restrict__ gb)
{
    int token = (blockIdx.x * blockDim.x + threadIdx.x) >> 5;
    int lane = threadIdx.x & 31;
    if (token >= N_TOK) return;
    const float* xr = x + (size_t)token * C_DIM;
    float acc = gb[lane];
#pragma unroll 4
    for (int k = 0; k < C_DIM; k++)
        acc = fmaf(xr[k], gw[k * E_NUM + lane], acc);
    float mx = acc;
#pragma unroll
    for (int o = 16; o > 0; o >>= 1) mx = fmaxf(mx, __shfl_xor_sync(0xffffffffu, mx, o));
    float ev = expf(acc - mx);
    float sm = ev;
#pragma unroll
    for (int o = 16; o > 0; o >>= 1) sm += __shfl_xor_sync(0xffffffffu, sm, o);
    g_gates[token * E_NUM + lane] = ev / sm;
}

// ---------------- main GEMM, cp.async 5-stage pipeline, 2 CTAs/SM -----------
// MODE 0: h = gate_e * gelu(x @ w1[e] + b1[e]) -> fp16   (grid z = expert)
// MODE 1: part[g] = sum_{e in g} h[e] @ w2[e]            (grid z = group of 4)
template<int MODE>
__global__ __launch_bounds__(256, 2) void council_mma(const float* __restrict__ bias)
{
    extern __shared__ __half smem[];
    const int t = threadIdx.x, lane = t & 31, wid = t >> 5;
    const int wm = wid & 3, wn = wid >> 2;
    const int m0 = blockIdx.x * BM, n0 = blockIdx.y * BN, z = blockIdx.z;

    const size_t ldA = (MODE == 0) ? C_DIM : H_DIM;
    const size_t ldB = (MODE == 0) ? H_DIM : C_DIM;
    const int kper = (int)(ldA / BK);                       // 24 or 96
    const int nstot = (MODE == 0) ? kper : (EPG * kper);    // 24 or 384

    float acc[2][8][4];
#pragma unroll
    for (int mi = 0; mi < 2; mi++)
#pragma unroll
        for (int n8 = 0; n8 < 8; n8++)
#pragma unroll
            for (int q = 0; q < 4; q++) acc[mi][n8][q] = 0.0f;

    auto issue = [&](int s) {
        const int slot = s % NSTAGES;
        const uint32_t sA = smem_u32(smem + (size_t)slot * STAGE_ELTS);
        const uint32_t sB = sA + A_ELTS * 2;
        int e, k0;
        if (MODE == 0) { e = z; k0 = s * BK; }
        else           { e = z * EPG + s / kper; k0 = (s % kper) * BK; }
        const __half* Ag = (MODE == 0) ? (g_x16 + (size_t)m0 * C_DIM)
                                       : (g_h16 + ((size_t)e * N_TOK + m0) * H_DIM);
        const __half* Bg = (MODE == 0) ? (g_w1h + (size_t)e * C_DIM * H_DIM + n0)
                                       : (g_w2h + (size_t)e * H_DIM * C_DIM + n0);
#pragma unroll
        for (int j = 0; j < 2; j++) {   // A: 128 rows x 4 chunks = 512 cp16 -> 2/thread
            int c = t + 256 * j;
            int r = c >> 2, kp = c & 3;
            cp16(sA + (r * ASTRIDE + kp * 8) * 2, Ag + (size_t)r * ldA + k0 + kp * 8);
        }
#pragma unroll
        for (int j = 0; j < 2; j++) {   // B: 32 rows x 16 chunks = 512 cp16 -> 2/thread
            int c = t + 256 * j;
            int rk = c >> 4, np = c & 15;
            cp16(sB + (rk * BSTRIDE + np * 8) * 2, Bg + (size_t)(k0 + rk) * ldB + np * 8);
        }
    };

    issue(0); CP_COMMIT;
    issue(1); CP_COMMIT;
    issue(2); CP_COMMIT;
    issue(3); CP_COMMIT;
    for (int s = 0; s < nstot; s++) {
        CP_WAIT3;
        __syncthreads();
        if (s + 4 < nstot) issue(s + 4);
        CP_COMMIT;
        const __half* st = smem + (size_t)(s % NSTAGES) * STAGE_ELTS;
        mma_stage(st, st + A_ELTS, lane, wm, wn, acc);
    }

    // ---- epilogue ----
    const int gid = lane >> 2, tg = lane & 3;
#pragma unroll
    for (int mi = 0; mi < 2; mi++) {
        int m = m0 + wm * 32 + mi * 16 + gid;
        if (MODE == 0) {
            float g0 = g_gates[m * E_NUM + z];
            float g1 = g_gates[(m + 8) * E_NUM + z];
#pragma unroll
            for (int n8 = 0; n8 < 8; n8++) {
                int n = n0 + wn * 64 + n8 * 8 + tg * 2;
                float b0 = bias[z * H_DIM + n], b1v = bias[z * H_DIM + n + 1];
                float* a = acc[mi][n8];
                size_t gi = ((size_t)z * N_TOK + m) * H_DIM + n;
                __half2 v0 = __floats2half2_rn(g0 * gelu_f(a[0] + b0), g0 * gelu_f(a[1] + b1v));
                __half2 v1 = __floats2half2_rn(g1 * gelu_f(a[2] + b0), g1 * gelu_f(a[3] + b1v));
                *reinterpret_cast<__half2*>(&g_h16[gi]) = v0;
                *reinterpret_cast<__half2*>(&g_h16[gi + (size_t)8 * H_DIM]) = v1;
            }
        } else {
#pragma unroll
            for (int n8 = 0; n8 < 8; n8++) {
                int n = n0 + wn * 64 + n8 * 8 + tg * 2;
                float* a = acc[mi][n8];
                size_t gi = (size_t)z * N_TOK * C_DIM + (size_t)m * C_DIM + n;
                *reinterpret_cast<float2*>(&g_part[gi]) = make_float2(a[0], a[1]);
                *reinterpret_cast<float2*>(&g_part[gi + (size_t)8 * C_DIM]) =
                    make_float2(a[2], a[3]);
            }
        }
    }
}

// ---------------- finalize: out = sum_g part[g] + sum_e gate*b2 --------------
__global__ void finalize_kernel(const float* __restrict__ b2, float* __restrict__ out)
{
    int i4 = blockIdx.x * 256 + threadIdx.x;
    if (i4 >= N_TOK * C_DIM / 4) return;
    int i = i4 * 4, m = i / C_DIM, c = i % C_DIM;
    float4 s = make_float4(0.f, 0.f, 0.f, 0.f);
#pragma unroll
    for (int g = 0; g < NGRP; g++) {
        float4 p = *(const float4*)&g_part[(size_t)g * N_TOK * C_DIM + i];
        s.x += p.x; s.y += p.y; s.z += p.z; s.w += p.w;
    }
    const float* gr = &g_gates[m * E_NUM];
#pragma unroll 8
    for (int e = 0; e < E_NUM; e++) {
        float g = gr[e];
        const float* bb = &b2[e * C_DIM + c];
        s.x += g * bb[0]; s.y += g * bb[1];
        s.z += g * bb[2]; s.w += g * bb[3];
    }
    *(float4*)&out[i] = s;
}

// ---------------- launch -----------------------------------------------------
extern "C" void kernel_launch(void* const* d_in, const int* in_sizes, int n_in,
                              void* d_out, int out_size)
{
    (void)in_sizes; (void)n_in; (void)out_size;
    const float* x      = (const float*)d_in[0];
    const float* gate_w = (const float*)d_in[1];
    const float* gate_b = (const float*)d_in[2];
    const float* w1     = (const float*)d_in[3];
    const float* b1     = (const float*)d_in[4];
    const float* w2     = (const float*)d_in[5];
    const float* b2     = (const float*)d_in[6];
    float* out = (float*)d_out;

    static int attr_done = 0;
    if (!attr_done) {
        cudaFuncSetAttribute(council_mma<0>, cudaFuncAttributeMaxDynamicSharedMemorySize, SMEM_BYTES);
        cudaFuncSetAttribute(council_mma<1>, cudaFuncAttributeMaxDynamicSharedMemorySize, SMEM_BYTES);
        attr_done = 1;
    }

    __half *xh, *w1h, *w2h;
    cudaGetSymbolAddress((void**)&xh,  g_x16);
    cudaGetSymbolAddress((void**)&w1h, g_w1h);
    cudaGetSymbolAddress((void**)&w2h, g_w2h);

    const int n4x = N_TOK * C_DIM / 4;
    const int n4w = (int)((size_t)E_NUM * C_DIM * H_DIM / 4);

    gate_kernel<<<N_TOK / 8, 256>>>(x, gate_w, gate_b);
    convert_kernel<<<(n4x + 255) / 256, 256>>>((const float4*)x, (uint2*)xh, n4x);
    convert2_kernel<<<(2 * n4w + 255) / 256, 256>>>((const float4*)w1, (uint2*)w1h,
                                                    (const float4*)w2, (uint2*)w2h, n4w);

    council_mma<0><<<dim3(N_TOK / BM, H_DIM / BN, E_NUM), 256, SMEM_BYTES>>>(b1);
    council_mma<1><<<dim3(N_TOK / BM, C_DIM / BN, NGRP), 256, SMEM_BYTES>>>(nullptr);
    finalize_kernel<<<(N_TOK * C_DIM / 4 + 255) / 256, 256>>>(b2, out);
}

// round 16
// speedup vs baseline: 1.2226x; 1.2226x over previous
#include <cuda_runtime.h>
#include <cuda_fp16.h>
#include <cstdint>
#include <math.h>

#define N_TOK 2048
#define C_DIM 768
#define E_NUM 32
#define H_DIM 3072

#define BM 128
#define BN 128
#define BK 32
#define ASTRIDE 40     // 80B rows: 16B-aligned; ldmatrix conflict-free
#define BSTRIDE 136    // 272B rows: 16B-aligned; ldmatrix.trans conflict-free

#define A_ELTS (BM * ASTRIDE)              // 5120
#define B_ELTS (BK * BSTRIDE)              // 4352
#define STAGE_ELTS (A_ELTS + B_ELTS)       // 9472 elts (fp16)
#define NSTAGES 5
#define SMEM_BYTES (NSTAGES * STAGE_ELTS * 2)  // 94720 B -> 2 CTAs/SM

// ---------------- scratch (device globals; no allocation allowed) -----------
__device__ float g_gates[N_TOK * E_NUM];
__device__ __half g_x16[N_TOK * C_DIM];
__device__ __half g_w1h[(size_t)E_NUM * C_DIM * H_DIM];
__device__ __half g_w2h[(size_t)E_NUM * H_DIM * C_DIM];
__device__ __half g_h16[(size_t)E_NUM * N_TOK * H_DIM];
__device__ float g_part[(size_t)E_NUM * N_TOK * C_DIM];

// ---------------- helpers ---------------------------------------------------
__device__ __forceinline__ uint32_t smem_u32(const void* p) {
    return (uint32_t)__cvta_generic_to_shared(p);
}
__device__ __forceinline__ void cp16(uint32_t s, const void* g) {
    asm volatile("cp.async.cg.shared.global [%0], [%1], 16;" :: "r"(s), "l"(g));
}
#define CP_COMMIT asm volatile("cp.async.commit_group;" ::: "memory")
#define CP_WAIT3  asm volatile("cp.async.wait_group 3;" ::: "memory")

__device__ __forceinline__ void ldm_x4(uint32_t r[4], uint32_t addr) {
    asm volatile("ldmatrix.sync.aligned.m8n8.x4.shared.b16 {%0,%1,%2,%3}, [%4];"
                 : "=r"(r[0]), "=r"(r[1]), "=r"(r[2]), "=r"(r[3]) : "r"(addr));
}
__device__ __forceinline__ void ldm_x4_t(uint32_t r[4], uint32_t addr) {
    asm volatile("ldmatrix.sync.aligned.m8n8.x4.trans.shared.b16 {%0,%1,%2,%3}, [%4];"
                 : "=r"(r[0]), "=r"(r[1]), "=r"(r[2]), "=r"(r[3]) : "r"(addr));
}
__device__ __forceinline__ void mma16816(float d[4], const uint32_t a[4], const uint32_t b[2]) {
    asm volatile("mma.sync.aligned.m16n8k16.row.col.f32.f16.f16.f32 "
                 "{%0,%1,%2,%3},{%4,%5,%6,%7},{%8,%9},{%0,%1,%2,%3};"
                 : "+f"(d[0]), "+f"(d[1]), "+f"(d[2]), "+f"(d[3])
                 : "r"(a[0]), "r"(a[1]), "r"(a[2]), "r"(a[3]), "r"(b[0]), "r"(b[1]));
}
__device__ __forceinline__ uint2 pack_h4(float4 v) {
    __half2 a = __floats2half2_rn(v.x, v.y);
    __half2 b = __floats2half2_rn(v.z, v.w);
    uint2 r;
    r.x = *reinterpret_cast<uint32_t*>(&a);
    r.y = *reinterpret_cast<uint32_t*>(&b);
    return r;
}
__device__ __forceinline__ float gelu_f(float v) {
    return 0.5f * v * (1.0f + erff(v * 0.70710678118654752f));
}

// single-pass fp16 MMA over one BK=32 stage.
// 4 warps 2(M)x2(N); per warp 64x64. 128B smem per HMMA (BW-balanced).
__device__ __forceinline__ void mma_stage(
    const __half* As, const __half* Bs,
    int lane, int wm, int wn, float acc[4][8][4])
{
#pragma unroll
    for (int kk = 0; kk < 2; kk++) {
        uint32_t a[4][4];
#pragma unroll
        for (int mi = 0; mi < 4; mi++) {
            int off = (wm * 64 + mi * 16 + (lane & 15)) * ASTRIDE + kk * 16 + ((lane >> 4) << 3);
            ldm_x4(a[mi], smem_u32(As + off));
        }
        uint32_t b[4][4];
#pragma unroll
        for (int nj = 0; nj < 4; nj++) {
            int off = (kk * 16 + (lane & 15)) * BSTRIDE + wn * 64 + nj * 16 + ((lane >> 4) << 3);
            ldm_x4_t(b[nj], smem_u32(Bs + off));
        }
#pragma unroll
        for (int mi = 0; mi < 4; mi++) {
#pragma unroll
            for (int n8 = 0; n8 < 8; n8++) {
                mma16816(acc[mi][n8], a[mi], &b[n8 >> 1][(n8 & 1) * 2]);
            }
        }
    }
}

// ---------------- converters -------------------------------------------------
__global__ void convert2_kernel(const float4* __restrict__ s0, uint2* __restrict__ d0,
                                const float4* __restrict__ s1, uint2* __restrict__ d1,
                                int n4)
{
    int i = blockIdx.x * blockDim.x + threadIdx.x;
    if (i < n4) d0[i] = pack_h4(s0[i]);
    else if (i < 2 * n4) d1[i - n4] = pack_h4(s1[i - n4]);
}
__global__ void convert_kernel(const float4* __restrict__ src,
                               uint2* __restrict__ dst, int n4)
{
    int i = blockIdx.x * blockDim.x + threadIdx.x;
    if (i >= n4) return;
    dst[i] = pack_h4(src[i]);
}

// ---------------- gating softmax ---------------------------------------------
__global__ void gate_kernel(const float* __restrict__ x,
                            const float* __restrict__ gw,
                            const float* __restrict__ gb)
{
    int token = (blockIdx.x * blockDim.x + threadIdx.x) >> 5;
    int lane = threadIdx.x & 31;
    if (token >= N_TOK) return;
    const float* xr = x + (size_t)token * C_DIM;
    float acc = gb[lane];
#pragma unroll 4
    for (int k = 0; k < C_DIM; k++)
        acc = fmaf(xr[k], gw[k * E_NUM + lane], acc);
    float mx = acc;
#pragma unroll
    for (int o = 16; o > 0; o >>= 1) mx = fmaxf(mx, __shfl_xor_sync(0xffffffffu, mx, o));
    float ev = expf(acc - mx);
    float sm = ev;
#pragma unroll
    for (int o = 16; o > 0; o >>= 1) sm += __shfl_xor_sync(0xffffffffu, sm, o);
    g_gates[token * E_NUM + lane] = ev / sm;
}

// ---------------- main GEMM: 128 threads, warp 64x64, 2 CTAs/SM --------------
// MODE 0: h = gelu(x @ w1[e] + b1[e]) -> fp16
// MODE 1: part[e] = gate * (h[e] @ w2[e])
template<int MODE>
__global__ __launch_bounds__(128, 2) void council_mma(const float* __restrict__ bias)
{
    extern __shared__ __half smem[];
    const int t = threadIdx.x, lane = t & 31, wid = t >> 5;
    const int wm = wid & 1, wn = wid >> 1;
    const int m0 = blockIdx.x * BM, n0 = blockIdx.y * BN, e = blockIdx.z;

    const size_t ldA = (MODE == 0) ? C_DIM : H_DIM;
    const size_t ldB = (MODE == 0) ? H_DIM : C_DIM;
    const int nstot = (int)(ldA / BK);   // 24 or 96

    const __half* Ag = (MODE == 0) ? (g_x16 + (size_t)m0 * C_DIM)
                                   : (g_h16 + ((size_t)e * N_TOK + m0) * H_DIM);
    const __half* Bg = (MODE == 0) ? (g_w1h + (size_t)e * C_DIM * H_DIM + n0)
                                   : (g_w2h + (size_t)e * H_DIM * C_DIM + n0);

    float acc[4][8][4];
#pragma unroll
    for (int mi = 0; mi < 4; mi++)
#pragma unroll
        for (int n8 = 0; n8 < 8; n8++)
#pragma unroll
            for (int q = 0; q < 4; q++) acc[mi][n8][q] = 0.0f;

    auto issue = [&](int s) {
        const int slot = s % NSTAGES;
        const uint32_t sA = smem_u32(smem + (size_t)slot * STAGE_ELTS);
        const uint32_t sB = sA + A_ELTS * 2;
        const int k0 = s * BK;
#pragma unroll
        for (int j = 0; j < 4; j++) {   // A: 128 rows x 4 chunks = 512 cp16 -> 4/thread
            int c = t + 128 * j;
            int r = c >> 2, kp = c & 3;
            cp16(sA + (r * ASTRIDE + kp * 8) * 2, Ag + (size_t)r * ldA + k0 + kp * 8);
        }
#pragma unroll
        for (int j = 0; j < 4; j++) {   // B: 32 rows x 16 chunks = 512 cp16 -> 4/thread
            int c = t + 128 * j;
            int rk = c >> 4, np = c & 15;
            cp16(sB + (rk * BSTRIDE + np * 8) * 2, Bg + (size_t)(k0 + rk) * ldB + np * 8);
        }
    };

    issue(0); CP_COMMIT;
    issue(1); CP_COMMIT;
    issue(2); CP_COMMIT;
    issue(3); CP_COMMIT;
    for (int s = 0; s < nstot; s++) {
        CP_WAIT3;
        __syncthreads();
        if (s + 4 < nstot) issue(s + 4);
        CP_COMMIT;
        const __half* st = smem + (size_t)(s % NSTAGES) * STAGE_ELTS;
        mma_stage(st, st + A_ELTS, lane, wm, wn, acc);
    }

    // ---- epilogue ----
    const int gid = lane >> 2, tg = lane & 3;
#pragma unroll
    for (int mi = 0; mi < 4; mi++) {
        int m = m0 + wm * 64 + mi * 16 + gid;
        if (MODE == 0) {
#pragma unroll
            for (int n8 = 0; n8 < 8; n8++) {
                int n = n0 + wn * 64 + n8 * 8 + tg * 2;
                float b0 = bias[e * H_DIM + n], b1v = bias[e * H_DIM + n + 1];
                float* a = acc[mi][n8];
                size_t gi = ((size_t)e * N_TOK + m) * H_DIM + n;
                __half2 v0 = __floats2half2_rn(gelu_f(a[0] + b0), gelu_f(a[1] + b1v));
                __half2 v1 = __floats2half2_rn(gelu_f(a[2] + b0), gelu_f(a[3] + b1v));
                *reinterpret_cast<__half2*>(&g_h16[gi]) = v0;
                *reinterpret_cast<__half2*>(&g_h16[gi + (size_t)8 * H_DIM]) = v1;
            }
        } else {
            float g0 = g_gates[m * E_NUM + e];
            float g1 = g_gates[(m + 8) * E_NUM + e];
#pragma unroll
            for (int n8 = 0; n8 < 8; n8++) {
                int n = n0 + wn * 64 + n8 * 8 + tg * 2;
                float* a = acc[mi][n8];
                size_t gi = (size_t)e * N_TOK * C_DIM + (size_t)m * C_DIM + n;
                *reinterpret_cast<float2*>(&g_part[gi]) = make_float2(a[0] * g0, a[1] * g0);
                *reinterpret_cast<float2*>(&g_part[gi + (size_t)8 * C_DIM]) =
                    make_float2(a[2] * g1, a[3] * g1);
            }
        }
    }
}

// ---------------- finalize ---------------------------------------------------
__global__ void finalize_kernel(const float* __restrict__ b2, float* __restrict__ out)
{
    int i4 = blockIdx.x * 256 + threadIdx.x;
    if (i4 >= N_TOK * C_DIM / 4) return;
    int i = i4 * 4, m = i / C_DIM, c = i % C_DIM;
    float4 s = make_float4(0.f, 0.f, 0.f, 0.f);
#pragma unroll 8
    for (int e = 0; e < E_NUM; e++) {
        float4 p = *(const float4*)&g_part[(size_t)e * N_TOK * C_DIM + i];
        float g = g_gates[m * E_NUM + e];
        const float* bb = &b2[e * C_DIM + c];
        s.x += p.x + g * bb[0]; s.y += p.y + g * bb[1];
        s.z += p.z + g * bb[2]; s.w += p.w + g * bb[3];
    }
    *(float4*)&out[i] = s;
}

// ---------------- launch -----------------------------------------------------
extern "C" void kernel_launch(void* const* d_in, const int* in_sizes, int n_in,
                              void* d_out, int out_size)
{
    (void)in_sizes; (void)n_in; (void)out_size;
    const float* x      = (const float*)d_in[0];
    const float* gate_w = (const float*)d_in[1];
    const float* gate_b = (const float*)d_in[2];
    const float* w1     = (const float*)d_in[3];
    const float* b1     = (const float*)d_in[4];
    const float* w2     = (const float*)d_in[5];
    const float* b2     = (const float*)d_in[6];
    float* out = (float*)d_out;

    static int attr_done = 0;
    if (!attr_done) {
        cudaFuncSetAttribute(council_mma<0>, cudaFuncAttributeMaxDynamicSharedMemorySize, SMEM_BYTES);
        cudaFuncSetAttribute(council_mma<1>, cudaFuncAttributeMaxDynamicSharedMemorySize, SMEM_BYTES);
        attr_done = 1;
    }

    __half *xh, *w1h, *w2h;
    cudaGetSymbolAddress((void**)&xh,  g_x16);
    cudaGetSymbolAddress((void**)&w1h, g_w1h);
    cudaGetSymbolAddress((void**)&w2h, g_w2h);

    const int n4x = N_TOK * C_DIM / 4;
    const int n4w = (int)((size_t)E_NUM * C_DIM * H_DIM / 4);

    gate_kernel<<<N_TOK / 8, 256>>>(x, gate_w, gate_b);
    convert_kernel<<<(n4x + 255) / 256, 256>>>((const float4*)x, (uint2*)xh, n4x);
    convert2_kernel<<<(2 * n4w + 255) / 256, 256>>>((const float4*)w1, (uint2*)w1h,
                                                    (const float4*)w2, (uint2*)w2h, n4w);

    council_mma<0><<<dim3(N_TOK / BM, H_DIM / BN, E_NUM), 128, SMEM_BYTES>>>(b1);
    council_mma<1><<<dim3(N_TOK / BM, C_DIM / BN, E_NUM), 128, SMEM_BYTES>>>(nullptr);
    finalize_kernel<<<(N_TOK * C_DIM / 4 + 255) / 256, 256>>>(b2, out);
}